// round 8
// baseline (speedup 1.0000x reference)
#include <cuda_runtime.h>
#include <math.h>

constexpr int NB = 64;
constexpr int NT = 12;
constexpr int ND = 256;
constexpr int NS = 512;
constexpr int NV = 512;
constexpr int GRAPH_STEPS = 3;

typedef unsigned long long ull;

// cross-kernel scratch (device globals; no allocation allowed)
__device__ float g_gates[2 * NB * NT];   // [g][b][t]
__device__ float g_gsT[512 * 64];        // [k][b]
__device__ float g_hT[2 * 256 * 64];     // [br][col][b]

__device__ __forceinline__ float gelu_f(float x) {
    return 0.5f * x * (1.0f + erff(x * 0.70710678118654752440f));
}
__device__ __forceinline__ float sigmoid_f(float x) {
    return 1.0f / (1.0f + expf(-x));
}

// ---- packed f32x2 helpers (sm_103a) ----
__device__ __forceinline__ ull pk2(float lo, float hi) {
    ull r; asm("mov.b64 %0, {%1, %2};" : "=l"(r) : "f"(lo), "f"(hi)); return r;
}
__device__ __forceinline__ ull fma2(ull a, ull b, ull c) {
    ull d; asm("fma.rn.f32x2 %0, %1, %2, %3;" : "=l"(d) : "l"(a), "l"(b), "l"(c)); return d;
}
__device__ __forceinline__ ull add2(ull a, ull b) {
    ull d; asm("add.rn.f32x2 %0, %1, %2;" : "=l"(d) : "l"(a), "l"(b)); return d;
}
__device__ __forceinline__ float2 upk(ull v) {
    float2 f; asm("mov.b64 {%0, %1}, %2;" : "=f"(f.x), "=f"(f.y) : "l"(v)); return f;
}

// ---------------------------------------------------------------------------
// Kernel 1: one gate MLP per block.  grid = 128 = (b, g), 1024 threads.
//   jp = tid&127 -> columns (2jp, 2jp+1);  kg = tid>>7 -> K-chunk of 32.
// Per k: LDG.64 weights + 3 broadcast LDS.128 (12 evidence rows, pair-packed)
// + 12 FFMA2.  8 K-partials combined via 2-slot pairwise smem tree.
// ---------------------------------------------------------------------------
__global__ void __launch_bounds__(1024, 1)
k_gates(const float* __restrict__ evidence,
        const float* __restrict__ Wmg1, const float* __restrict__ bmg1,
        const float* __restrict__ Wmg2, const float* __restrict__ bmg2,
        const float* __restrict__ Wsg1, const float* __restrict__ bsg1,
        const float* __restrict__ Wsg2, const float* __restrict__ bsg2)
{
    __shared__ __align__(16) float xT[ND * NT];   // 12 KB  xT[k][r]
    __shared__ ull  comb[2][12][128];             // 24 KB  combine slots
    __shared__ float red[NT][4];

    const int b  = blockIdx.x >> 1;
    const int g  = blockIdx.x & 1;
    const int tid = threadIdx.x;
    const int jp = tid & 127;
    const int kg = tid >> 7;        // 0..7

    const float* __restrict__ W1 = g ? Wsg1 : Wmg1;
    const float* __restrict__ B1 = g ? bsg1 : bmg1;
    const float* __restrict__ W2 = g ? Wsg2 : Wmg2;
    const float* __restrict__ B2 = g ? bsg2 : bmg2;

    // transpose evidence: j = tid&255 owns col j; q = tid>>8 rows 3q..3q+2
    {
        const int j = tid & 255, q = tid >> 8;
        #pragma unroll
        for (int r = q * 3; r < q * 3 + 3; r++)
            xT[j * NT + r] = evidence[(b * NT + r) * ND + j];
    }
    __syncthreads();

    // ---- K-loop: 32 k, 2 columns, 12 rows ----
    ull a0[6], a1[6];
    #pragma unroll
    for (int i = 0; i < 6; i++) { a0[i] = 0ull; a1[i] = 0ull; }
    {
        const int k0 = kg * 32;
        #pragma unroll 8
        for (int kk = 0; kk < 32; kk++) {
            const int k = k0 + kk;
            const float2 w = *(const float2*)&W1[k * ND + 2 * jp];
            const ull wp0 = pk2(w.x, w.x);
            const ull wp1 = pk2(w.y, w.y);
            const ulonglong2* xp = (const ulonglong2*)(xT + k * NT);
            const ulonglong2 p0 = xp[0];
            const ulonglong2 p1 = xp[1];
            const ulonglong2 p2 = xp[2];
            a0[0] = fma2(p0.x, wp0, a0[0]);  a1[0] = fma2(p0.x, wp1, a1[0]);
            a0[1] = fma2(p0.y, wp0, a0[1]);  a1[1] = fma2(p0.y, wp1, a1[1]);
            a0[2] = fma2(p1.x, wp0, a0[2]);  a1[2] = fma2(p1.x, wp1, a1[2]);
            a0[3] = fma2(p1.y, wp0, a0[3]);  a1[3] = fma2(p1.y, wp1, a1[3]);
            a0[4] = fma2(p2.x, wp0, a0[4]);  a1[4] = fma2(p2.x, wp1, a1[4]);
            a0[5] = fma2(p2.y, wp0, a0[5]);  a1[5] = fma2(p2.y, wp1, a1[5]);
        }
    }

    // ---- pairwise combine 8 -> 1 (2 slots) ----
    // r1a: kg4,5 -> slots; kg0,1 add
    if (kg == 4 || kg == 5) {
        #pragma unroll
        for (int i = 0; i < 6; i++) { comb[kg - 4][i][jp] = a0[i]; comb[kg - 4][6 + i][jp] = a1[i]; }
    }
    __syncthreads();
    if (kg == 0 || kg == 1) {
        #pragma unroll
        for (int i = 0; i < 6; i++) { a0[i] = add2(a0[i], comb[kg][i][jp]); a1[i] = add2(a1[i], comb[kg][6 + i][jp]); }
    }
    __syncthreads();
    // r1b: kg6,7 -> slots; kg2,3 add
    if (kg == 6 || kg == 7) {
        #pragma unroll
        for (int i = 0; i < 6; i++) { comb[kg - 6][i][jp] = a0[i]; comb[kg - 6][6 + i][jp] = a1[i]; }
    }
    __syncthreads();
    if (kg == 2 || kg == 3) {
        #pragma unroll
        for (int i = 0; i < 6; i++) { a0[i] = add2(a0[i], comb[kg - 2][i][jp]); a1[i] = add2(a1[i], comb[kg - 2][6 + i][jp]); }
    }
    __syncthreads();
    // r2: kg2,3 -> slots; kg0,1 add
    if (kg == 2 || kg == 3) {
        #pragma unroll
        for (int i = 0; i < 6; i++) { comb[kg - 2][i][jp] = a0[i]; comb[kg - 2][6 + i][jp] = a1[i]; }
    }
    __syncthreads();
    if (kg == 0 || kg == 1) {
        #pragma unroll
        for (int i = 0; i < 6; i++) { a0[i] = add2(a0[i], comb[kg][i][jp]); a1[i] = add2(a1[i], comb[kg][6 + i][jp]); }
    }
    __syncthreads();
    // r3: kg1 -> slot0; kg0 add
    if (kg == 1) {
        #pragma unroll
        for (int i = 0; i < 6; i++) { comb[0][i][jp] = a0[i]; comb[0][6 + i][jp] = a1[i]; }
    }
    __syncthreads();

    if (kg == 0) {
        #pragma unroll
        for (int i = 0; i < 6; i++) { a0[i] = add2(a0[i], comb[0][i][jp]); a1[i] = add2(a1[i], comb[0][6 + i][jp]); }

        const float b10 = B1[2 * jp],  b11 = B1[2 * jp + 1];
        const float w20 = W2[2 * jp],  w21 = W2[2 * jp + 1];
        const int lane = jp & 31, warp = jp >> 5;
        #pragma unroll
        for (int i = 0; i < 6; i++) {
            const float2 f0 = upk(a0[i]), f1 = upk(a1[i]);
            float ve = gelu_f(f0.x + b10) * w20 + gelu_f(f1.x + b11) * w21;
            float vo = gelu_f(f0.y + b10) * w20 + gelu_f(f1.y + b11) * w21;
            #pragma unroll
            for (int off = 16; off > 0; off >>= 1) {
                ve += __shfl_xor_sync(0xffffffffu, ve, off);
                vo += __shfl_xor_sync(0xffffffffu, vo, off);
            }
            if (lane == 0) { red[2 * i][warp] = ve; red[2 * i + 1][warp] = vo; }
        }
    }
    __syncthreads();

    if (tid < NT) {
        const float s = red[tid][0] + red[tid][1] + red[tid][2] + red[tid][3];
        g_gates[(g * NB + b) * NT + tid] = sigmoid_f(s + B2[0]);
    }
}

// ---------------------------------------------------------------------------
// Kernel 2: sparse graph readout -> gsT.  grid = 64, 512 threads.
// ---------------------------------------------------------------------------
__global__ void __launch_bounds__(512, 2)
k_graph(const int* __restrict__ em,  const int* __restrict__ si,
        const int* __restrict__ sv,  const int* __restrict__ tsi,
        const int* __restrict__ tsv, const int* __restrict__ tvi,
        const int* __restrict__ tvv, const int* __restrict__ qi,
        const int* __restrict__ qv,
        const float* __restrict__ symbol_emb,
        const float* __restrict__ value_emb)
{
    __shared__ float walk[NS], nwalk[NS], wsum[NS], vw[NV];
    __shared__ int   e_msrc[NT], e_mtgt[NT], e_ssrc[NT], e_stgt[NT];
    __shared__ float e_mval[NT], e_sval[NT];
    __shared__ int   scand[NT + 1], vcand[NT];
    __shared__ int   n_scand, n_vcand;

    const int b   = blockIdx.x;
    const int tid = threadIdx.x;

    walk[tid] = 0.f;  wsum[tid] = 0.f;  vw[tid] = 0.f;
    if (tid < NT) {
        const int t   = tid;
        const int mk  = em [b * NT + t];
        const int src = si [b * NT + t];
        const int svv = sv [b * NT + t];
        const int ts  = tsi[b * NT + t];
        const int tsx = tsv[b * NT + t];
        const int tv  = tvi[b * NT + t];
        const int tvx = tvv[b * NT + t];
        const int src_c = min(max(src, 0), NS - 1);
        const int ts_c  = min(max(ts,  0), NS - 1);
        const int tv_c  = min(max(tv,  0), NV - 1);
        const bool mm = ((mk == 0) || (mk == 1)) && (svv > 0) && (tvx > 0);
        const bool sm = (mk == 2) && (svv > 0) && (tsx > 0);
        e_msrc[t] = src_c; e_mtgt[t] = tv_c; e_mval[t] = mm ? g_gates[b * NT + t]        : 0.f;
        e_ssrc[t] = src_c; e_stgt[t] = ts_c; e_sval[t] = sm ? g_gates[(NB + b) * NT + t] : 0.f;
    }
    __syncthreads();

    if (tid == 0) {
        const int q = min(max(qi[b], 0), NS - 1);
        if (qv[b] > 0) walk[q] = 1.0f;
        int n = 0;
        scand[n++] = q;
        for (int t = 0; t < NT; t++) {
            const int c = e_stgt[t];
            bool dup = false;
            for (int k = 0; k < n; k++) dup |= (scand[k] == c);
            if (!dup) scand[n++] = c;
        }
        n_scand = n;
        int m = 0;
        for (int t = 0; t < NT; t++) {
            const int c = e_mtgt[t];
            bool dup = false;
            for (int k = 0; k < m; k++) dup |= (vcand[k] == c);
            if (!dup) vcand[m++] = c;
        }
        n_vcand = m;
    }
    __syncthreads();

    // walk evolution, warp 0 only (support <= 13)
    if (tid < 32) {
        const int nsc = n_scand;
        for (int iter = 0; iter <= GRAPH_STEPS; iter++) {
            if (tid < nsc) wsum[scand[tid]] += walk[scand[tid]];
            if (tid < NT) {
                const float c = walk[e_msrc[tid]] * e_mval[tid];
                if (c != 0.f) atomicAdd(&vw[e_mtgt[tid]], c);
            }
            __syncwarp();
            if (iter < GRAPH_STEPS) {
                if (tid < nsc) nwalk[scand[tid]] = 0.f;
                __syncwarp();
                if (tid < NT) {
                    const float c = walk[e_ssrc[tid]] * e_sval[tid];
                    if (c != 0.f) atomicAdd(&nwalk[e_stgt[tid]], c);
                }
                __syncwarp();
                if (tid < nsc) walk[scand[tid]] = nwalk[scand[tid]];
                __syncwarp();
            }
        }
    }
    __syncthreads();

    // sparse gather -> gsT[k][b]
    {
        float rres;
        if (tid < 256) {
            float accs = 0.f;
            const int nsc = n_scand;
            for (int c = 0; c < nsc; c++) {
                const int s = scand[c];
                accs = fmaf(wsum[s], symbol_emb[s * ND + tid], accs);
            }
            rres = accs;
        } else {
            const int d = tid - 256;
            float vpart = 0.f;
            const int nvc = n_vcand;
            for (int c = 0; c < nvc; c++) {
                const int v = vcand[c];
                vpart = fmaf(vw[v], value_emb[v * ND + d], vpart);
            }
            rres = vpart;
        }
        g_gsT[tid * 64 + b] = rres;
    }
}

// ---------------------------------------------------------------------------
// Kernel 3: layer-1 batch-shared GEMM + gelu.  grid = 128, 1024 threads.
// ---------------------------------------------------------------------------
__global__ void __launch_bounds__(1024, 1)
k_l1(const float* __restrict__ Wf1, const float* __restrict__ bf1,
     const float* __restrict__ Wo1, const float* __restrict__ bo1)
{
    __shared__ ull part[1024];
    const int bid = blockIdx.x;
    const int br  = bid >> 6;
    const int t   = bid & 63;
    const int tid = threadIdx.x;

    const float* __restrict__ W1 = br ? Wo1 : Wf1;
    const float* __restrict__ B1 = br ? bo1 : bf1;

    const int ks = tid >> 7;
    const int rem = tid & 127;
    const int c  = rem >> 5;
    const int bp = rem & 31;
    const int gcol = t * 4 + c;

    ull acc = 0ull;
    const int k0 = ks * 64;
    #pragma unroll 8
    for (int kk = 0; kk < 64; kk++) {
        const int k = k0 + kk;
        const float wv = W1[k * ND + gcol];
        const ull av = *(const ull*)(g_gsT + k * 64 + 2 * bp);
        acc = fma2(av, pk2(wv, wv), acc);
    }
    part[tid] = acc;
    __syncthreads();

    if (tid < 128) {
        float s0 = 0.f, s1 = 0.f;
        #pragma unroll
        for (int k2 = 0; k2 < 8; k2++) {
            const float2 f = upk(part[k2 * 128 + tid]);
            s0 += f.x; s1 += f.y;
        }
        const int c2 = tid >> 5, bp2 = tid & 31;
        const int col = t * 4 + c2;
        const float bb = B1[col];
        float2 hv;
        hv.x = gelu_f(s0 + bb);
        hv.y = gelu_f(s1 + bb);
        *(float2*)(g_hT + (br * 256 + col) * 64 + 2 * bp2) = hv;
    }
}

// ---------------------------------------------------------------------------
// Kernel 4: layer-2 batch-shared GEMMs + bias -> out.  grid = 96, 1024 thr.
// ---------------------------------------------------------------------------
__global__ void __launch_bounds__(1024, 1)
k_l2(const float* __restrict__ Wf2, const float* __restrict__ bf2,
     const float* __restrict__ Wo2, const float* __restrict__ bo2,
     float* __restrict__ out)
{
    __shared__ ull part[1024];
    const int bid = blockIdx.x;
    const int tid = threadIdx.x;
    const bool lg = (bid < 64);
    const int t = lg ? bid : (bid - 64);

    const int ks = tid >> 8;
    const int rem = tid & 255;
    const int c  = rem >> 5;
    const int bp = rem & 31;
    const int gcol = t * 8 + c;

    const float* __restrict__ W = lg ? Wo2 : Wf2;
    const int wstride = lg ? NV : ND;
    const int hbase   = lg ? 256 : 0;

    ull acc = 0ull;
    const int k0 = ks * 64;
    #pragma unroll 8
    for (int kk = 0; kk < 64; kk++) {
        const int k = k0 + kk;
        const float wv = W[k * wstride + gcol];
        const ull av = *(const ull*)(g_hT + (hbase + k) * 64 + 2 * bp);
        acc = fma2(av, pk2(wv, wv), acc);
    }
    part[tid] = acc;
    __syncthreads();

    if (tid < 256) {
        float s0 = 0.f, s1 = 0.f;
        #pragma unroll
        for (int k2 = 0; k2 < 4; k2++) {
            const float2 f = upk(part[k2 * 256 + tid]);
            s0 += f.x; s1 += f.y;
        }
        const int c2 = tid >> 5, bp2 = tid & 31;
        const int col = t * 8 + c2;
        if (lg) {
            const float bb = bo2[col];
            out[(2 * bp2) * NV + col]     = s0 + bb;
            out[(2 * bp2 + 1) * NV + col] = s1 + bb;
        } else {
            const float bb = bf2[col];
            out[NB * NV + (2 * bp2) * ND + col]     = s0 + bb;
            out[NB * NV + (2 * bp2 + 1) * ND + col] = s1 + bb;
        }
    }
}

// ---------------------------------------------------------------------------
extern "C" void kernel_launch(void* const* d_in, const int* in_sizes, int n_in,
                              void* d_out, int out_size)
{
    const int*   event_marker       = (const int*)  d_in[0];
    const int*   source_idx         = (const int*)  d_in[1];
    const int*   source_valid       = (const int*)  d_in[2];
    const int*   target_symbol_idx  = (const int*)  d_in[3];
    const int*   target_symbol_vld  = (const int*)  d_in[4];
    const int*   target_value_idx   = (const int*)  d_in[5];
    const int*   target_value_vld   = (const int*)  d_in[6];
    const int*   query_idx          = (const int*)  d_in[7];
    const int*   query_valid        = (const int*)  d_in[8];
    const float* evidence           = (const float*)d_in[9];
    const float* symbol_emb         = (const float*)d_in[10];
    const float* value_emb          = (const float*)d_in[11];
    const float* Wmg1 = (const float*)d_in[12];
    const float* bmg1 = (const float*)d_in[13];
    const float* Wmg2 = (const float*)d_in[14];
    const float* bmg2 = (const float*)d_in[15];
    const float* Wsg1 = (const float*)d_in[16];
    const float* bsg1 = (const float*)d_in[17];
    const float* Wsg2 = (const float*)d_in[18];
    const float* bsg2 = (const float*)d_in[19];
    const float* Wf1  = (const float*)d_in[20];
    const float* bf1  = (const float*)d_in[21];
    const float* Wf2  = (const float*)d_in[22];
    const float* bf2  = (const float*)d_in[23];
    const float* Wo1  = (const float*)d_in[24];
    const float* bo1  = (const float*)d_in[25];
    const float* Wo2  = (const float*)d_in[26];
    const float* bo2  = (const float*)d_in[27];

    float* out = (float*)d_out;

    k_gates<<<2 * NB, 1024>>>(evidence, Wmg1, bmg1, Wmg2, bmg2,
                              Wsg1, bsg1, Wsg2, bsg2);
    k_graph<<<NB, 512>>>(event_marker, source_idx, source_valid,
                         target_symbol_idx, target_symbol_vld,
                         target_value_idx, target_value_vld,
                         query_idx, query_valid, symbol_emb, value_emb);
    k_l1<<<128, 1024>>>(Wf1, bf1, Wo1, bo1);
    k_l2<<<96, 1024>>>(Wf2, bf2, Wo2, bo2, out);
}

// round 9
// speedup vs baseline: 1.4709x; 1.4709x over previous
#include <cuda_runtime.h>
#include <math.h>

constexpr int NB = 64;
constexpr int NT = 12;
constexpr int ND = 256;
constexpr int NS = 512;
constexpr int NV = 512;
constexpr int GRAPH_STEPS = 3;

typedef unsigned long long ull;

// cross-kernel scratch: gate partial sums [colhalf][(g*NB+b)*NT+t]
__device__ float g_part[2][2 * NB * NT];

__device__ __forceinline__ float gelu_f(float x) {
    return 0.5f * x * (1.0f + erff(x * 0.70710678118654752440f));
}
__device__ __forceinline__ float sigmoid_f(float x) {
    return 1.0f / (1.0f + expf(-x));
}

// ---- packed f32x2 helpers (sm_103a) ----
__device__ __forceinline__ ull pk2(float lo, float hi) {
    ull r; asm("mov.b64 %0, {%1, %2};" : "=l"(r) : "f"(lo), "f"(hi)); return r;
}
__device__ __forceinline__ ull fma2(ull a, ull b, ull c) {
    ull d; asm("fma.rn.f32x2 %0, %1, %2, %3;" : "=l"(d) : "l"(a), "l"(b), "l"(c)); return d;
}
__device__ __forceinline__ ull add2(ull a, ull b) {
    ull d; asm("add.rn.f32x2 %0, %1, %2;" : "=l"(d) : "l"(a), "l"(b)); return d;
}
__device__ __forceinline__ float2 upk(ull v) {
    float2 f; asm("mov.b64 {%0, %1}, %2;" : "=f"(f.x), "=f"(f.y) : "l"(v)); return f;
}

// ---------------------------------------------------------------------------
// Kernel A: gate MLPs, batch-pair packed.
// grid = 128 = bpair(32) x gate(2) x colhalf(2), 1024 threads.
//   jp = tid&127 -> col j = ch*128+jp;  kg = tid>>7 -> K-chunk of 32.
// Each FFMA2 lane carries (batchA, batchB).  Writes col-half partial row sums
// to g_part (sigmoid deferred to kernel B).
// ---------------------------------------------------------------------------
__global__ void __launch_bounds__(1024, 1)
k_gates(const float* __restrict__ evidence,
        const float* __restrict__ Wmg1, const float* __restrict__ bmg1,
        const float* __restrict__ Wmg2,
        const float* __restrict__ Wsg1, const float* __restrict__ bsg1,
        const float* __restrict__ Wsg2)
{
    __shared__ __align__(16) char ubuf[24576];   // ev2 (24KB) then comb slots
    __shared__ float red[2][NT][4];

    const int bid = blockIdx.x;
    const int p  = bid >> 2;          // batch pair
    const int g  = (bid >> 1) & 1;    // gate
    const int ch = bid & 1;           // col half
    const int bA = 2 * p, bB = 2 * p + 1;
    const int tid = threadIdx.x;

    const float* __restrict__ W1 = g ? Wsg1 : Wmg1;
    const float* __restrict__ B1 = g ? bsg1 : bmg1;
    const float* __restrict__ W2 = g ? Wsg2 : Wmg2;

    // pack evidence for both batches: ev2[k][r] = (evA[r][k], evB[r][k])
    ull* ev2 = (ull*)ubuf;
    {
        const int k = tid & 255, q = tid >> 8;
        #pragma unroll
        for (int r = q * 3; r < q * 3 + 3; r++)
            ev2[k * NT + r] = pk2(evidence[(bA * NT + r) * ND + k],
                                  evidence[(bB * NT + r) * ND + k]);
    }
    __syncthreads();

    const int jp = tid & 127;
    const int kg = tid >> 7;          // 0..7
    const int j  = ch * 128 + jp;

    ull acc[NT];
    #pragma unroll
    for (int i = 0; i < NT; i++) acc[i] = 0ull;
    {
        const int k0 = kg * 32;
        #pragma unroll 4
        for (int kk = 0; kk < 32; kk++) {
            const int k = k0 + kk;
            const float w = W1[k * ND + j];
            const ull wp = pk2(w, w);
            const ulonglong2* xp = (const ulonglong2*)(ev2 + k * NT);
            {
                const ulonglong2 q0 = xp[0], q1 = xp[1], q2 = xp[2];
                acc[0] = fma2(q0.x, wp, acc[0]);
                acc[1] = fma2(q0.y, wp, acc[1]);
                acc[2] = fma2(q1.x, wp, acc[2]);
                acc[3] = fma2(q1.y, wp, acc[3]);
                acc[4] = fma2(q2.x, wp, acc[4]);
                acc[5] = fma2(q2.y, wp, acc[5]);
            }
            {
                const ulonglong2 q3 = xp[3], q4 = xp[4], q5 = xp[5];
                acc[6]  = fma2(q3.x, wp, acc[6]);
                acc[7]  = fma2(q3.y, wp, acc[7]);
                acc[8]  = fma2(q4.x, wp, acc[8]);
                acc[9]  = fma2(q4.y, wp, acc[9]);
                acc[10] = fma2(q5.x, wp, acc[10]);
                acc[11] = fma2(q5.y, wp, acc[11]);
            }
        }
    }
    __syncthreads();   // ev2 reads done; ubuf becomes combine slots

    ull (*comb)[NT][128] = (ull (*)[NT][128])ubuf;   // [2 slots][12][128]

    // pairwise combine 8 -> 1 (proven sequence)
    if (kg == 4 || kg == 5) {
        #pragma unroll
        for (int i = 0; i < NT; i++) comb[kg - 4][i][jp] = acc[i];
    }
    __syncthreads();
    if (kg == 0 || kg == 1) {
        #pragma unroll
        for (int i = 0; i < NT; i++) acc[i] = add2(acc[i], comb[kg][i][jp]);
    }
    __syncthreads();
    if (kg == 6 || kg == 7) {
        #pragma unroll
        for (int i = 0; i < NT; i++) comb[kg - 6][i][jp] = acc[i];
    }
    __syncthreads();
    if (kg == 2 || kg == 3) {
        #pragma unroll
        for (int i = 0; i < NT; i++) acc[i] = add2(acc[i], comb[kg - 2][i][jp]);
    }
    __syncthreads();
    if (kg == 2 || kg == 3) {
        #pragma unroll
        for (int i = 0; i < NT; i++) comb[kg - 2][i][jp] = acc[i];
    }
    __syncthreads();
    if (kg == 0 || kg == 1) {
        #pragma unroll
        for (int i = 0; i < NT; i++) acc[i] = add2(acc[i], comb[kg][i][jp]);
    }
    __syncthreads();
    if (kg == 1) {
        #pragma unroll
        for (int i = 0; i < NT; i++) comb[0][i][jp] = acc[i];
    }
    __syncthreads();

    if (kg == 0) {
        #pragma unroll
        for (int i = 0; i < NT; i++) acc[i] = add2(acc[i], comb[0][i][jp]);

        const float b1 = B1[j];
        const float w2 = W2[j];
        const int lane = jp & 31, warp = jp >> 5;
        #pragma unroll
        for (int r = 0; r < NT; r++) {
            const float2 f = upk(acc[r]);
            float yA = gelu_f(f.x + b1) * w2;
            float yB = gelu_f(f.y + b1) * w2;
            #pragma unroll
            for (int off = 16; off > 0; off >>= 1) {
                yA += __shfl_xor_sync(0xffffffffu, yA, off);
                yB += __shfl_xor_sync(0xffffffffu, yB, off);
            }
            if (lane == 0) { red[0][r][warp] = yA; red[1][r][warp] = yB; }
        }
    }
    __syncthreads();

    if (tid < 24) {
        const int bsel = tid / NT, t = tid % NT;
        const float s = red[bsel][t][0] + red[bsel][t][1] + red[bsel][t][2] + red[bsel][t][3];
        g_part[ch][(g * NB + (2 * p + bsel)) * NT + t] = s;
    }
}

// ---------------------------------------------------------------------------
// Kernel B: sparse graph + output MLPs, batch-pair packed.
// grid = 64 = bpair(32) x branch(2), 1024 threads.
// Gates finalized in-block; walk evolution: warp0 = batchA, warp1 = batchB;
// gs2[k] = (gsA, gsB) packed; layer1/2 FFMA2 with pair-packed activations.
// ---------------------------------------------------------------------------
__global__ void __launch_bounds__(1024, 1)
k_graph_out(const int* __restrict__ em,  const int* __restrict__ si,
            const int* __restrict__ sv,  const int* __restrict__ tsi,
            const int* __restrict__ tsv, const int* __restrict__ tvi,
            const int* __restrict__ tvv, const int* __restrict__ qi,
            const int* __restrict__ qv,
            const float* __restrict__ symbol_emb,
            const float* __restrict__ value_emb,
            const float* __restrict__ bmg2, const float* __restrict__ bsg2,
            const float* __restrict__ Wf1, const float* __restrict__ bf1,
            const float* __restrict__ Wf2, const float* __restrict__ bf2,
            const float* __restrict__ Wo1, const float* __restrict__ bo1,
            const float* __restrict__ Wo2, const float* __restrict__ bo2,
            float* __restrict__ out)
{
    __shared__ float walk[2][NS], nwalk[2][NS], wsum[2][NS], vw[2][NV];  // 16KB
    __shared__ ull   gs2[2 * ND];     // 4KB  (gsA, gsB) per k
    __shared__ ull   h2[ND];          // 2KB  hidden, pair-packed
    __shared__ ull   comb[2][2][256]; // 8KB  combine slots
    __shared__ float gate_s[2][2][NT];
    __shared__ int   e_msrc[2][NT], e_mtgt[2][NT], e_ssrc[2][NT], e_stgt[2][NT];
    __shared__ float e_mval[2][NT], e_sval[2][NT];
    __shared__ int   scand[2][NT + 1], vcand[2][NT];
    __shared__ int   n_scand[2], n_vcand[2];

    const int bid = blockIdx.x;
    const int p   = bid >> 1;
    const int br  = bid & 1;
    const int bA  = 2 * p;
    const int tid = threadIdx.x;

    // zero walk arrays (3 x 2 x 512 floats, 1024 threads -> 3 each)
    {
        float* z = &walk[0][0];
        z[tid] = 0.f;                       // walk
        (&wsum[0][0])[tid] = 0.f;
        (&vw[0][0])[tid] = 0.f;
    }
    // gate scalars for both gates x both batches
    if (tid < 48) {
        const int g = tid / 24, rem = tid % 24;
        const int bsel = rem / NT, t = rem % NT;
        const int b = bA + bsel;
        const float b2 = g ? bsg2[0] : bmg2[0];
        gate_s[g][bsel][t] = sigmoid_f(g_part[0][(g * NB + b) * NT + t]
                                     + g_part[1][(g * NB + b) * NT + t] + b2);
    }
    // edge indices + validity
    if (tid >= 64 && tid < 88) {
        const int u = tid - 64;
        const int bsel = u / NT, t = u % NT;
        const int b = bA + bsel;
        const int mk  = em [b * NT + t];
        const int src = si [b * NT + t];
        const int svv = sv [b * NT + t];
        const int ts  = tsi[b * NT + t];
        const int tsx = tsv[b * NT + t];
        const int tv  = tvi[b * NT + t];
        const int tvx = tvv[b * NT + t];
        const int src_c = min(max(src, 0), NS - 1);
        const int ts_c  = min(max(ts,  0), NS - 1);
        const int tv_c  = min(max(tv,  0), NV - 1);
        const bool mm = ((mk == 0) || (mk == 1)) && (svv > 0) && (tvx > 0);
        const bool sm = (mk == 2) && (svv > 0) && (tsx > 0);
        e_msrc[bsel][t] = src_c; e_mtgt[bsel][t] = tv_c; e_mval[bsel][t] = mm ? 1.f : 0.f;
        e_ssrc[bsel][t] = src_c; e_stgt[bsel][t] = ts_c; e_sval[bsel][t] = sm ? 1.f : 0.f;
    }
    __syncthreads();

    // dedup candidate lists + walk init (2 threads, one per batch)
    if (tid < 2) {
        const int bsel = tid;
        const int b = bA + bsel;
        const int q = min(max(qi[b], 0), NS - 1);
        if (qv[b] > 0) walk[bsel][q] = 1.0f;
        int n = 0;
        scand[bsel][n++] = q;
        for (int t = 0; t < NT; t++) {
            const int c = e_stgt[bsel][t];
            bool dup = false;
            for (int k = 0; k < n; k++) dup |= (scand[bsel][k] == c);
            if (!dup) scand[bsel][n++] = c;
        }
        n_scand[bsel] = n;
        int m = 0;
        for (int t = 0; t < NT; t++) {
            const int c = e_mtgt[bsel][t];
            bool dup = false;
            for (int k = 0; k < m; k++) dup |= (vcand[bsel][k] == c);
            if (!dup) vcand[bsel][m++] = c;
        }
        n_vcand[bsel] = m;
    }
    // apply gates to edge values
    if (tid >= 32 && tid < 56) {
        const int u = tid - 32;
        const int bsel = u / NT, t = u % NT;
        e_mval[bsel][t] *= gate_s[0][bsel][t];
        e_sval[bsel][t] *= gate_s[1][bsel][t];
    }
    __syncthreads();

    // walk evolution: warp 0 = batch A, warp 1 = batch B
    if (tid < 64) {
        const int w = tid >> 5;      // bsel
        const int lane = tid & 31;
        const int nsc = n_scand[w];
        for (int iter = 0; iter <= GRAPH_STEPS; iter++) {
            if (lane < nsc) wsum[w][scand[w][lane]] += walk[w][scand[w][lane]];
            if (lane < NT) {
                const float c = walk[w][e_msrc[w][lane]] * e_mval[w][lane];
                if (c != 0.f) atomicAdd(&vw[w][e_mtgt[w][lane]], c);
            }
            __syncwarp();
            if (iter < GRAPH_STEPS) {
                if (lane < nsc) nwalk[w][scand[w][lane]] = 0.f;
                __syncwarp();
                if (lane < NT) {
                    const float c = walk[w][e_ssrc[w][lane]] * e_sval[w][lane];
                    if (c != 0.f) atomicAdd(&nwalk[w][e_stgt[w][lane]], c);
                }
                __syncwarp();
                if (lane < nsc) walk[w][scand[w][lane]] = nwalk[w][scand[w][lane]];
                __syncwarp();
            }
        }
    }
    __syncthreads();

    // sparse gather -> gs2[k] = (gsA[k], gsB[k])
    if (tid < 512) {
        float rA, rB;
        if (tid < 256) {
            const int d = tid;
            float a0 = 0.f, a1 = 0.f;
            const int n0 = n_scand[0], n1 = n_scand[1];
            for (int c = 0; c < n0; c++) {
                const int s = scand[0][c];
                a0 = fmaf(wsum[0][s], symbol_emb[s * ND + d], a0);
            }
            for (int c = 0; c < n1; c++) {
                const int s = scand[1][c];
                a1 = fmaf(wsum[1][s], symbol_emb[s * ND + d], a1);
            }
            rA = a0; rB = a1;
        } else {
            const int d = tid - 256;
            float a0 = 0.f, a1 = 0.f;
            const int n0 = n_vcand[0], n1 = n_vcand[1];
            for (int c = 0; c < n0; c++) {
                const int v = vcand[0][c];
                a0 = fmaf(vw[0][v], value_emb[v * ND + d], a0);
            }
            for (int c = 0; c < n1; c++) {
                const int v = vcand[1][c];
                a1 = fmaf(vw[1][v], value_emb[v * ND + d], a1);
            }
            rA = a0; rB = a1;
        }
        gs2[tid] = pk2(rA, rB);
    }
    __syncthreads();

    // ---- layer 1: 2 cols/thread, 8-way K-split (K=512) ----
    const float* __restrict__ W1 = br ? Wo1 : Wf1;
    const float* __restrict__ B1 = br ? bo1 : bf1;
    {
        const int jp = tid & 127;         // cols 2jp, 2jp+1
        const int kg = tid >> 7;          // 0..7, 64 k each
        ull a0 = 0ull, a1 = 0ull;
        const int k0 = kg * 64;
        #pragma unroll 8
        for (int kk = 0; kk < 64; kk++) {
            const int k = k0 + kk;
            const float2 w = *(const float2*)&W1[k * ND + 2 * jp];
            const ull av = gs2[k];
            a0 = fma2(av, pk2(w.x, w.x), a0);
            a1 = fma2(av, pk2(w.y, w.y), a1);
        }
        // combine 8 -> 1 (payload 2)
        if (kg == 4 || kg == 5) { comb[kg - 4][0][jp] = a0; comb[kg - 4][1][jp] = a1; }
        __syncthreads();
        if (kg == 0 || kg == 1) { a0 = add2(a0, comb[kg][0][jp]); a1 = add2(a1, comb[kg][1][jp]); }
        __syncthreads();
        if (kg == 6 || kg == 7) { comb[kg - 6][0][jp] = a0; comb[kg - 6][1][jp] = a1; }
        __syncthreads();
        if (kg == 2 || kg == 3) { a0 = add2(a0, comb[kg - 2][0][jp]); a1 = add2(a1, comb[kg - 2][1][jp]); }
        __syncthreads();
        if (kg == 2 || kg == 3) { comb[kg - 2][0][jp] = a0; comb[kg - 2][1][jp] = a1; }
        __syncthreads();
        if (kg == 0 || kg == 1) { a0 = add2(a0, comb[kg][0][jp]); a1 = add2(a1, comb[kg][1][jp]); }
        __syncthreads();
        if (kg == 1) { comb[0][0][jp] = a0; comb[0][1][jp] = a1; }
        __syncthreads();
        if (kg == 0) {
            a0 = add2(a0, comb[0][0][jp]);
            a1 = add2(a1, comb[0][1][jp]);
            const float2 f0 = upk(a0), f1 = upk(a1);
            const float bb0 = B1[2 * jp], bb1 = B1[2 * jp + 1];
            h2[2 * jp]     = pk2(gelu_f(f0.x + bb0), gelu_f(f0.y + bb0));
            h2[2 * jp + 1] = pk2(gelu_f(f1.x + bb1), gelu_f(f1.y + bb1));
        }
    }
    __syncthreads();

    // ---- layer 2 ----
    if (br) {
        // logits: 512 cols -> 256 col-pairs, 4-way K-split (64 k each)
        const int cp = tid & 255;
        const int kg = tid >> 8;          // 0..3
        ull a0 = 0ull, a1 = 0ull;
        const int k0 = kg * 64;
        #pragma unroll 8
        for (int kk = 0; kk < 64; kk++) {
            const int k = k0 + kk;
            const float2 w = *(const float2*)&Wo2[k * NV + 2 * cp];
            const ull av = h2[k];
            a0 = fma2(av, pk2(w.x, w.x), a0);
            a1 = fma2(av, pk2(w.y, w.y), a1);
        }
        if (kg == 2 || kg == 3) { comb[kg - 2][0][cp] = a0; comb[kg - 2][1][cp] = a1; }
        __syncthreads();
        if (kg == 0 || kg == 1) { a0 = add2(a0, comb[kg][0][cp]); a1 = add2(a1, comb[kg][1][cp]); }
        __syncthreads();
        if (kg == 1) { comb[0][0][cp] = a0; comb[0][1][cp] = a1; }
        __syncthreads();
        if (kg == 0) {
            a0 = add2(a0, comb[0][0][cp]);
            a1 = add2(a1, comb[0][1][cp]);
            const float2 f0 = upk(a0), f1 = upk(a1);
            const int c0 = 2 * cp, c1 = 2 * cp + 1;
            const float bb0 = bo2[c0], bb1 = bo2[c1];
            out[bA * NV + c0]       = f0.x + bb0;
            out[(bA + 1) * NV + c0] = f0.y + bb0;
            out[bA * NV + c1]       = f1.x + bb1;
            out[(bA + 1) * NV + c1] = f1.y + bb1;
        }
    } else {
        // feedback: 256 cols -> 128 col-pairs, 8-way K-split (32 k each)
        const int cp = tid & 127;
        const int kg = tid >> 7;          // 0..7
        ull a0 = 0ull, a1 = 0ull;
        const int k0 = kg * 32;
        #pragma unroll 8
        for (int kk = 0; kk < 32; kk++) {
            const int k = k0 + kk;
            const float2 w = *(const float2*)&Wf2[k * ND + 2 * cp];
            const ull av = h2[k];
            a0 = fma2(av, pk2(w.x, w.x), a0);
            a1 = fma2(av, pk2(w.y, w.y), a1);
        }
        if (kg == 4 || kg == 5) { comb[kg - 4][0][cp] = a0; comb[kg - 4][1][cp] = a1; }
        __syncthreads();
        if (kg == 0 || kg == 1) { a0 = add2(a0, comb[kg][0][cp]); a1 = add2(a1, comb[kg][1][cp]); }
        __syncthreads();
        if (kg == 6 || kg == 7) { comb[kg - 6][0][cp] = a0; comb[kg - 6][1][cp] = a1; }
        __syncthreads();
        if (kg == 2 || kg == 3) { a0 = add2(a0, comb[kg - 2][0][cp]); a1 = add2(a1, comb[kg - 2][1][cp]); }
        __syncthreads();
        if (kg == 2 || kg == 3) { comb[kg - 2][0][cp] = a0; comb[kg - 2][1][cp] = a1; }
        __syncthreads();
        if (kg == 0 || kg == 1) { a0 = add2(a0, comb[kg][0][cp]); a1 = add2(a1, comb[kg][1][cp]); }
        __syncthreads();
        if (kg == 1) { comb[0][0][cp] = a0; comb[0][1][cp] = a1; }
        __syncthreads();
        if (kg == 0) {
            a0 = add2(a0, comb[0][0][cp]);
            a1 = add2(a1, comb[0][1][cp]);
            const float2 f0 = upk(a0), f1 = upk(a1);
            const int c0 = 2 * cp, c1 = 2 * cp + 1;
            const float bb0 = bf2[c0], bb1 = bf2[c1];
            out[NB * NV + bA * ND + c0]       = f0.x + bb0;
            out[NB * NV + (bA + 1) * ND + c0] = f0.y + bb0;
            out[NB * NV + bA * ND + c1]       = f1.x + bb1;
            out[NB * NV + (bA + 1) * ND + c1] = f1.y + bb1;
        }
    }
}

// ---------------------------------------------------------------------------
extern "C" void kernel_launch(void* const* d_in, const int* in_sizes, int n_in,
                              void* d_out, int out_size)
{
    const int*   event_marker       = (const int*)  d_in[0];
    const int*   source_idx         = (const int*)  d_in[1];
    const int*   source_valid       = (const int*)  d_in[2];
    const int*   target_symbol_idx  = (const int*)  d_in[3];
    const int*   target_symbol_vld  = (const int*)  d_in[4];
    const int*   target_value_idx   = (const int*)  d_in[5];
    const int*   target_value_vld   = (const int*)  d_in[6];
    const int*   query_idx          = (const int*)  d_in[7];
    const int*   query_valid        = (const int*)  d_in[8];
    const float* evidence           = (const float*)d_in[9];
    const float* symbol_emb         = (const float*)d_in[10];
    const float* value_emb          = (const float*)d_in[11];
    const float* Wmg1 = (const float*)d_in[12];
    const float* bmg1 = (const float*)d_in[13];
    const float* Wmg2 = (const float*)d_in[14];
    const float* bmg2 = (const float*)d_in[15];
    const float* Wsg1 = (const float*)d_in[16];
    const float* bsg1 = (const float*)d_in[17];
    const float* Wsg2 = (const float*)d_in[18];
    const float* bsg2 = (const float*)d_in[19];
    const float* Wf1  = (const float*)d_in[20];
    const float* bf1  = (const float*)d_in[21];
    const float* Wf2  = (const float*)d_in[22];
    const float* bf2  = (const float*)d_in[23];
    const float* Wo1  = (const float*)d_in[24];
    const float* bo1  = (const float*)d_in[25];
    const float* Wo2  = (const float*)d_in[26];
    const float* bo2  = (const float*)d_in[27];

    float* out = (float*)d_out;

    k_gates<<<128, 1024>>>(evidence, Wmg1, bmg1, Wmg2, Wsg1, bsg1, Wsg2);
    k_graph_out<<<64, 1024>>>(event_marker, source_idx, source_valid,
                              target_symbol_idx, target_symbol_vld,
                              target_value_idx, target_value_vld,
                              query_idx, query_valid,
                              symbol_emb, value_emb,
                              bmg2, bsg2,
                              Wf1, bf1, Wf2, bf2,
                              Wo1, bo1, Wo2, bo2, out);
}

// round 10
// speedup vs baseline: 1.8453x; 1.2545x over previous
#include <cuda_runtime.h>
#include <math.h>

constexpr int NB = 64;
constexpr int NT = 12;
constexpr int ND = 256;
constexpr int NS = 512;
constexpr int NV = 512;
constexpr int GRAPH_STEPS = 3;

typedef unsigned long long ull;

// cross-kernel scratch: gate partial sums [colhalf][(g*NB+b)*NT+t]
__device__ float g_part[2][2 * NB * NT];

__device__ __forceinline__ float gelu_f(float x) {
    return 0.5f * x * (1.0f + erff(x * 0.70710678118654752440f));
}
__device__ __forceinline__ float sigmoid_f(float x) {
    return 1.0f / (1.0f + expf(-x));
}

// ---- packed f32x2 helpers (sm_103a) ----
__device__ __forceinline__ ull pk2(float lo, float hi) {
    ull r; asm("mov.b64 %0, {%1, %2};" : "=l"(r) : "f"(lo), "f"(hi)); return r;
}
__device__ __forceinline__ ull fma2(ull a, ull b, ull c) {
    ull d; asm("fma.rn.f32x2 %0, %1, %2, %3;" : "=l"(d) : "l"(a), "l"(b), "l"(c)); return d;
}
__device__ __forceinline__ ull add2(ull a, ull b) {
    ull d; asm("add.rn.f32x2 %0, %1, %2;" : "=l"(d) : "l"(a), "l"(b)); return d;
}
__device__ __forceinline__ float2 upk(ull v) {
    float2 f; asm("mov.b64 {%0, %1}, %2;" : "=f"(f.x), "=f"(f.y) : "l"(v)); return f;
}

// ---------------------------------------------------------------------------
// Kernel A: gate MLPs, batch-pair packed (proven round-9 structure) + zeroes
// the output buffer for kernel B's atomic accumulation.
// grid = 128 = bpair(32) x gate(2) x colhalf(2), 1024 threads.
// ---------------------------------------------------------------------------
__global__ void __launch_bounds__(1024, 1)
k_gates(const float* __restrict__ evidence,
        const float* __restrict__ Wmg1, const float* __restrict__ bmg1,
        const float* __restrict__ Wmg2,
        const float* __restrict__ Wsg1, const float* __restrict__ bsg1,
        const float* __restrict__ Wsg2,
        float* __restrict__ out)
{
    __shared__ __align__(16) char ubuf[24576];   // ev2 (24KB) then comb slots
    __shared__ float red[2][NT][4];

    const int bid = blockIdx.x;
    const int p  = bid >> 2;          // batch pair
    const int g  = (bid >> 1) & 1;    // gate
    const int ch = bid & 1;           // col half
    const int bA = 2 * p, bB = 2 * p + 1;
    const int tid = threadIdx.x;

    // zero out (48K floats / 128 blocks = 384 each) for kernel B atomics
    if (tid < 384) out[bid * 384 + tid] = 0.f;

    const float* __restrict__ W1 = g ? Wsg1 : Wmg1;
    const float* __restrict__ B1 = g ? bsg1 : bmg1;
    const float* __restrict__ W2 = g ? Wsg2 : Wmg2;

    // pack evidence for both batches: ev2[k][r] = (evA[r][k], evB[r][k])
    ull* ev2 = (ull*)ubuf;
    {
        const int k = tid & 255, q = tid >> 8;
        #pragma unroll
        for (int r = q * 3; r < q * 3 + 3; r++)
            ev2[k * NT + r] = pk2(evidence[(bA * NT + r) * ND + k],
                                  evidence[(bB * NT + r) * ND + k]);
    }
    __syncthreads();

    const int jp = tid & 127;
    const int kg = tid >> 7;          // 0..7
    const int j  = ch * 128 + jp;

    ull acc[NT];
    #pragma unroll
    for (int i = 0; i < NT; i++) acc[i] = 0ull;
    {
        const int k0 = kg * 32;
        #pragma unroll 4
        for (int kk = 0; kk < 32; kk++) {
            const int k = k0 + kk;
            const float w = W1[k * ND + j];
            const ull wp = pk2(w, w);
            const ulonglong2* xp = (const ulonglong2*)(ev2 + k * NT);
            {
                const ulonglong2 q0 = xp[0], q1 = xp[1], q2 = xp[2];
                acc[0] = fma2(q0.x, wp, acc[0]);
                acc[1] = fma2(q0.y, wp, acc[1]);
                acc[2] = fma2(q1.x, wp, acc[2]);
                acc[3] = fma2(q1.y, wp, acc[3]);
                acc[4] = fma2(q2.x, wp, acc[4]);
                acc[5] = fma2(q2.y, wp, acc[5]);
            }
            {
                const ulonglong2 q3 = xp[3], q4 = xp[4], q5 = xp[5];
                acc[6]  = fma2(q3.x, wp, acc[6]);
                acc[7]  = fma2(q3.y, wp, acc[7]);
                acc[8]  = fma2(q4.x, wp, acc[8]);
                acc[9]  = fma2(q4.y, wp, acc[9]);
                acc[10] = fma2(q5.x, wp, acc[10]);
                acc[11] = fma2(q5.y, wp, acc[11]);
            }
        }
    }
    __syncthreads();   // ev2 reads done; ubuf becomes combine slots

    // single-shot combine: all kg != 0 store, one sync, kg0 adds 7
    ull (*comb)[NT][128] = (ull (*)[NT][128])ubuf;   // [8 slots][12][128] = 24KB? 8*12*128*8 = 98KB no!
    // NOTE: 8 slots won't fit; use the proven pairwise tree (2 slots, 24KB OK).
    if (kg == 4 || kg == 5) {
        #pragma unroll
        for (int i = 0; i < NT; i++) comb[kg - 4][i][jp] = acc[i];
    }
    __syncthreads();
    if (kg == 0 || kg == 1) {
        #pragma unroll
        for (int i = 0; i < NT; i++) acc[i] = add2(acc[i], comb[kg][i][jp]);
    }
    __syncthreads();
    if (kg == 6 || kg == 7) {
        #pragma unroll
        for (int i = 0; i < NT; i++) comb[kg - 6][i][jp] = acc[i];
    }
    __syncthreads();
    if (kg == 2 || kg == 3) {
        #pragma unroll
        for (int i = 0; i < NT; i++) acc[i] = add2(acc[i], comb[kg - 2][i][jp]);
    }
    __syncthreads();
    if (kg == 2 || kg == 3) {
        #pragma unroll
        for (int i = 0; i < NT; i++) comb[kg - 2][i][jp] = acc[i];
    }
    __syncthreads();
    if (kg == 0 || kg == 1) {
        #pragma unroll
        for (int i = 0; i < NT; i++) acc[i] = add2(acc[i], comb[kg][i][jp]);
    }
    __syncthreads();
    if (kg == 1) {
        #pragma unroll
        for (int i = 0; i < NT; i++) comb[0][i][jp] = acc[i];
    }
    __syncthreads();

    if (kg == 0) {
        #pragma unroll
        for (int i = 0; i < NT; i++) acc[i] = add2(acc[i], comb[0][i][jp]);

        const float b1 = B1[j];
        const float w2 = W2[j];
        const int lane = jp & 31, warp = jp >> 5;
        #pragma unroll
        for (int r = 0; r < NT; r++) {
            const float2 f = upk(acc[r]);
            float yA = gelu_f(f.x + b1) * w2;
            float yB = gelu_f(f.y + b1) * w2;
            #pragma unroll
            for (int off = 16; off > 0; off >>= 1) {
                yA += __shfl_xor_sync(0xffffffffu, yA, off);
                yB += __shfl_xor_sync(0xffffffffu, yB, off);
            }
            if (lane == 0) { red[0][r][warp] = yA; red[1][r][warp] = yB; }
        }
    }
    __syncthreads();

    if (tid < 24) {
        const int bsel = tid / NT, t = tid % NT;
        const float s = red[bsel][t][0] + red[bsel][t][1] + red[bsel][t][2] + red[bsel][t][3];
        g_part[ch][(g * NB + (2 * p + bsel)) * NT + t] = s;
    }
}

// ---------------------------------------------------------------------------
// Kernel B: sparse graph + output MLPs, batch-pair packed.
// grid = 128 = bpair(32) x branch(2) x colhalf(2), 1024 threads.
// Each block: gates finalize + graph (warp-parallel dedup) + gather (dup per
// ch) -> layer1 for its 128-col half (full K) -> layer2 partial over its
// h-half for ALL output cols, atomically accumulated into zeroed out.
// ---------------------------------------------------------------------------
__global__ void __launch_bounds__(1024, 1)
k_graph_out(const int* __restrict__ em,  const int* __restrict__ si,
            const int* __restrict__ sv,  const int* __restrict__ tsi,
            const int* __restrict__ tsv, const int* __restrict__ tvi,
            const int* __restrict__ tvv, const int* __restrict__ qi,
            const int* __restrict__ qv,
            const float* __restrict__ symbol_emb,
            const float* __restrict__ value_emb,
            const float* __restrict__ bmg2, const float* __restrict__ bsg2,
            const float* __restrict__ Wf1, const float* __restrict__ bf1,
            const float* __restrict__ Wf2, const float* __restrict__ bf2,
            const float* __restrict__ Wo1, const float* __restrict__ bo1,
            const float* __restrict__ Wo2, const float* __restrict__ bo2,
            float* __restrict__ out)
{
    __shared__ __align__(16) char ubuf[16384];   // walk arrays, then comb slots
    __shared__ ull   gs2[2 * ND];                // 4KB  (gsA, gsB) per k
    __shared__ ull   h2[128];                    // 1KB  this block's h col-half
    __shared__ float gate_s[2][2][NT];
    __shared__ int   e_msrc[2][NT], e_mtgt[2][NT], e_stgt[2][NT];
    __shared__ float e_mval[2][NT], e_sval[2][NT];
    __shared__ int   scand[2][16], vcand[2][16];
    __shared__ int   n_scand[2], n_vcand[2];

    const int bid = blockIdx.x;
    const int p   = bid >> 2;
    const int br  = (bid >> 1) & 1;
    const int ch  = bid & 1;
    const int bA  = 2 * p;
    const int tid = threadIdx.x;

    float* walk  = (float*)ubuf;          // [2][512]
    float* nwalk = walk + 1024;
    float* wsum  = walk + 2048;
    float* vw    = walk + 3072;

    walk[tid] = 0.f;  wsum[tid] = 0.f;  vw[tid] = 0.f;

    // gate scalars for both gates x both batches
    if (tid < 48) {
        const int g = tid / 24, rem = tid % 24;
        const int bsel = rem / NT, t = rem % NT;
        const int b = bA + bsel;
        const float b2 = g ? bsg2[0] : bmg2[0];
        gate_s[g][bsel][t] = sigmoid_f(g_part[0][(g * NB + b) * NT + t]
                                     + g_part[1][(g * NB + b) * NT + t] + b2);
    }
    // edge indices + validity
    if (tid >= 64 && tid < 88) {
        const int u = tid - 64;
        const int bsel = u / NT, t = u % NT;
        const int b = bA + bsel;
        const int mk  = em [b * NT + t];
        const int src = si [b * NT + t];
        const int svv = sv [b * NT + t];
        const int ts  = tsi[b * NT + t];
        const int tsx = tsv[b * NT + t];
        const int tv  = tvi[b * NT + t];
        const int tvx = tvv[b * NT + t];
        const int src_c = min(max(src, 0), NS - 1);
        const int ts_c  = min(max(ts,  0), NS - 1);
        const int tv_c  = min(max(tv,  0), NV - 1);
        const bool mm = ((mk == 0) || (mk == 1)) && (svv > 0) && (tvx > 0);
        const bool sm = (mk == 2) && (svv > 0) && (tsx > 0);
        e_msrc[bsel][t] = src_c; e_mtgt[bsel][t] = tv_c; e_mval[bsel][t] = mm ? 1.f : 0.f;
        e_stgt[bsel][t] = ts_c;  e_sval[bsel][t] = sm ? 1.f : 0.f;
    }
    __syncthreads();

    // warp-parallel dedup: warp0/1 = scand A/B, warp2/3 = vcand A/B
    if (tid < 128) {
        const int w = tid >> 5, lane = tid & 31;
        const int bsel = w & 1;
        const bool is_s = (w < 2);
        const int b = bA + bsel;
        int cand = 0x10000 + lane;    // unique sentinel for inactive lanes
        bool active = false;
        if (is_s) {
            if (lane == 0) {
                const int q = min(max(qi[b], 0), NS - 1);
                cand = q; active = true;
                if (qv[b] > 0) walk[bsel * NS + q] = 1.0f;
            } else if (lane < 13) {
                cand = e_stgt[bsel][lane - 1]; active = true;
            }
        } else {
            if (lane < 12) { cand = e_mtgt[bsel][lane]; active = true; }
        }
        const unsigned m = __match_any_sync(0xffffffffu, cand);
        const bool keep = active && ((m & ((1u << lane) - 1u)) == 0u);
        const unsigned keepmask = __ballot_sync(0xffffffffu, keep);
        if (keep) {
            const int idx = __popc(keepmask & ((1u << lane) - 1u));
            if (is_s) scand[bsel][idx] = cand; else vcand[bsel][idx] = cand;
        }
        if (lane == 0) {
            if (is_s) n_scand[bsel] = __popc(keepmask);
            else      n_vcand[bsel] = __popc(keepmask);
        }
    }
    // apply gates to edge values
    if (tid >= 128 && tid < 152) {
        const int u = tid - 128;
        const int bsel = u / NT, t = u % NT;
        e_mval[bsel][t] *= gate_s[0][bsel][t];
        e_sval[bsel][t] *= gate_s[1][bsel][t];
    }
    __syncthreads();

    // walk evolution: warp 0 = batch A, warp 1 = batch B
    if (tid < 64) {
        const int w = tid >> 5;
        const int lane = tid & 31;
        float* wk = walk + w * NS;
        float* nw = nwalk + w * NS;
        float* ws = wsum + w * NS;
        float* vv = vw + w * NS;
        const int nsc = n_scand[w];
        for (int iter = 0; iter <= GRAPH_STEPS; iter++) {
            if (lane < nsc) ws[scand[w][lane]] += wk[scand[w][lane]];
            if (lane < NT) {
                const float c = wk[e_msrc[w][lane]] * e_mval[w][lane];
                if (c != 0.f) atomicAdd(&vv[e_mtgt[w][lane]], c);
            }
            __syncwarp();
            if (iter < GRAPH_STEPS) {
                if (lane < nsc) nw[scand[w][lane]] = 0.f;
                __syncwarp();
                if (lane < NT) {
                    const float c = wk[e_msrc[w][lane]] * e_sval[w][lane];
                    if (c != 0.f) atomicAdd(&nw[e_stgt[w][lane]], c);
                }
                __syncwarp();
                if (lane < nsc) wk[scand[w][lane]] = nw[scand[w][lane]];
                __syncwarp();
            }
        }
    }
    __syncthreads();

    // sparse gather -> gs2[k] = (gsA[k], gsB[k])  (duplicated per ch)
    if (tid < 512) {
        float rA, rB;
        if (tid < 256) {
            const int d = tid;
            float a0 = 0.f, a1 = 0.f;
            const int n0 = n_scand[0], n1 = n_scand[1];
            for (int c = 0; c < n0; c++) {
                const int s = scand[0][c];
                a0 = fmaf(wsum[s], symbol_emb[s * ND + d], a0);
            }
            for (int c = 0; c < n1; c++) {
                const int s = scand[1][c];
                a1 = fmaf(wsum[NS + s], symbol_emb[s * ND + d], a1);
            }
            rA = a0; rB = a1;
        } else {
            const int d = tid - 256;
            float a0 = 0.f, a1 = 0.f;
            const int n0 = n_vcand[0], n1 = n_vcand[1];
            for (int c = 0; c < n0; c++) {
                const int v = vcand[0][c];
                a0 = fmaf(vw[v], value_emb[v * ND + d], a0);
            }
            for (int c = 0; c < n1; c++) {
                const int v = vcand[1][c];
                a1 = fmaf(vw[NS + v], value_emb[v * ND + d], a1);
            }
            rA = a0; rB = a1;
        }
        gs2[tid] = pk2(rA, rB);
    }
    __syncthreads();

    ull* comb = (ull*)ubuf;   // walk arrays dead; 2048 ull slots (16KB)

    // ---- layer 1: this block's 128-col half, full K=512 ----
    const float* __restrict__ W1 = br ? Wo1 : Wf1;
    const float* __restrict__ B1 = br ? bo1 : bf1;
    {
        const int cp = tid & 63;          // col pair within half
        const int kg = tid >> 6;          // 0..15, 32 k each
        const int j0 = ch * 128 + 2 * cp;
        ull a0 = 0ull, a1 = 0ull;
        const int k0 = kg * 32;
        #pragma unroll 8
        for (int kk = 0; kk < 32; kk++) {
            const int k = k0 + kk;
            const float2 w = *(const float2*)&W1[k * ND + j0];
            const ull av = gs2[k];
            a0 = fma2(av, pk2(w.x, w.x), a0);
            a1 = fma2(av, pk2(w.y, w.y), a1);
        }
        comb[(kg * 2 + 0) * 64 + cp] = a0;
        comb[(kg * 2 + 1) * 64 + cp] = a1;
    }
    __syncthreads();
    if (tid < 128) {
        const int cp = tid & 63, pay = tid >> 6;
        ull s = comb[(0 * 2 + pay) * 64 + cp];
        #pragma unroll
        for (int kg = 1; kg < 16; kg++)
            s = add2(s, comb[(kg * 2 + pay) * 64 + cp]);
        const int col = ch * 128 + 2 * cp + pay;
        const float2 f = upk(s);
        const float bb = B1[col];
        h2[2 * cp + pay] = pk2(gelu_f(f.x + bb), gelu_f(f.y + bb));
    }
    __syncthreads();

    // ---- layer 2: K = this block's 128 h entries, ALL output cols ----
    if (br) {
        // logits: 512 cols -> 256 col-pairs; kg = 4 x 32 k
        const int cp = tid & 255;
        const int kg = tid >> 8;
        const int kbase = ch * 128;
        ull a0 = 0ull, a1 = 0ull;
        const int k0 = kg * 32;
        #pragma unroll 8
        for (int kk = 0; kk < 32; kk++) {
            const int k = k0 + kk;
            const float2 w = *(const float2*)&Wo2[(kbase + k) * NV + 2 * cp];
            const ull av = h2[k];
            a0 = fma2(av, pk2(w.x, w.x), a0);
            a1 = fma2(av, pk2(w.y, w.y), a1);
        }
        comb[(kg * 2 + 0) * 256 + cp] = a0;
        comb[(kg * 2 + 1) * 256 + cp] = a1;
        __syncthreads();
        if (tid < 512) {
            const int cp2 = tid & 255, pay = tid >> 8;
            ull s = comb[(0 * 2 + pay) * 256 + cp2];
            #pragma unroll
            for (int kg2 = 1; kg2 < 4; kg2++)
                s = add2(s, comb[(kg2 * 2 + pay) * 256 + cp2]);
            const int col = 2 * cp2 + pay;
            float2 f = upk(s);
            if (ch == 0) { const float bb = bo2[col]; f.x += bb; f.y += bb; }
            atomicAdd(&out[bA * NV + col], f.x);
            atomicAdd(&out[(bA + 1) * NV + col], f.y);
        }
    } else {
        // feedback: 256 cols -> 128 col-pairs; kg = 8 x 16 k
        const int cp = tid & 127;
        const int kg = tid >> 7;
        const int kbase = ch * 128;
        ull a0 = 0ull, a1 = 0ull;
        const int k0 = kg * 16;
        #pragma unroll 8
        for (int kk = 0; kk < 16; kk++) {
            const int k = k0 + kk;
            const float2 w = *(const float2*)&Wf2[(kbase + k) * ND + 2 * cp];
            const ull av = h2[k];
            a0 = fma2(av, pk2(w.x, w.x), a0);
            a1 = fma2(av, pk2(w.y, w.y), a1);
        }
        comb[(kg * 2 + 0) * 128 + cp] = a0;
        comb[(kg * 2 + 1) * 128 + cp] = a1;
        __syncthreads();
        if (tid < 256) {
            const int cp2 = tid & 127, pay = tid >> 7;
            ull s = comb[(0 * 2 + pay) * 128 + cp2];
            #pragma unroll
            for (int kg2 = 1; kg2 < 8; kg2++)
                s = add2(s, comb[(kg2 * 2 + pay) * 128 + cp2]);
            const int col = 2 * cp2 + pay;
            float2 f = upk(s);
            if (ch == 0) { const float bb = bf2[col]; f.x += bb; f.y += bb; }
            atomicAdd(&out[NB * NV + bA * ND + col], f.x);
            atomicAdd(&out[NB * NV + (bA + 1) * ND + col], f.y);
        }
    }
}

// ---------------------------------------------------------------------------
extern "C" void kernel_launch(void* const* d_in, const int* in_sizes, int n_in,
                              void* d_out, int out_size)
{
    const int*   event_marker       = (const int*)  d_in[0];
    const int*   source_idx         = (const int*)  d_in[1];
    const int*   source_valid       = (const int*)  d_in[2];
    const int*   target_symbol_idx  = (const int*)  d_in[3];
    const int*   target_symbol_vld  = (const int*)  d_in[4];
    const int*   target_value_idx   = (const int*)  d_in[5];
    const int*   target_value_vld   = (const int*)  d_in[6];
    const int*   query_idx          = (const int*)  d_in[7];
    const int*   query_valid        = (const int*)  d_in[8];
    const float* evidence           = (const float*)d_in[9];
    const float* symbol_emb         = (const float*)d_in[10];
    const float* value_emb          = (const float*)d_in[11];
    const float* Wmg1 = (const float*)d_in[12];
    const float* bmg1 = (const float*)d_in[13];
    const float* Wmg2 = (const float*)d_in[14];
    const float* bmg2 = (const float*)d_in[15];
    const float* Wsg1 = (const float*)d_in[16];
    const float* bsg1 = (const float*)d_in[17];
    const float* Wsg2 = (const float*)d_in[18];
    const float* bsg2 = (const float*)d_in[19];
    const float* Wf1  = (const float*)d_in[20];
    const float* bf1  = (const float*)d_in[21];
    const float* Wf2  = (const float*)d_in[22];
    const float* bf2  = (const float*)d_in[23];
    const float* Wo1  = (const float*)d_in[24];
    const float* bo1  = (const float*)d_in[25];
    const float* Wo2  = (const float*)d_in[26];
    const float* bo2  = (const float*)d_in[27];

    float* out = (float*)d_out;

    k_gates<<<128, 1024>>>(evidence, Wmg1, bmg1, Wmg2, Wsg1, bsg1, Wsg2, out);
    k_graph_out<<<128, 1024>>>(event_marker, source_idx, source_valid,
                               target_symbol_idx, target_symbol_vld,
                               target_value_idx, target_value_vld,
                               query_idx, query_valid,
                               symbol_emb, value_emb,
                               bmg2, bsg2,
                               Wf1, bf1, Wf2, bf2,
                               Wo1, bo1, Wo2, bo2, out);
}